// round 17
// baseline (speedup 1.0000x reference)
#include <cuda_runtime.h>
#include <cuda_fp16.h>
#include <cuda_pipeline.h>
#include <mma.h>
#include <cstdint>
using namespace nvcuda;
#define EPSF 1e-5f
// B=8192, C=64, H=8, W=16, P=128, F5=8192

// ---------------- scratch ----------------
__device__ __half g_w2t[36864];                         // conv2 w [tap][o][c] fp16
__device__ __half g_w3[524288];                         // lc3 w [p][o][c] fp16
__device__ __half g_w4[524288];                         // lc4 w [p][o][c] fp16
__device__ __half g_w5[4194304];                        // fc5 w [n][p*64+c] fp16
__device__ __half g_w6[262144];                         // fc6 w [n][k] fp16
__device__ __half g_w7[65536];                          // fc7 w [n][k] fp16
__device__ __half g_a1[67108864];                       // conv1 out [p][b][c] fp16
__device__ __half g_a4[67108864];                       // lc4 out [b][p*64+c] fp16
__device__ __half g_a5[4194304];                        // fc5 out fp16
__device__ __half g_a6[4194304];                        // fc6 out fp16
__device__ float  g_a7[1048576];                        // fc7 out f32

__device__ __forceinline__ uint32_t packh2(__half a, __half b) {
    __half2 h = __halves2half2(a, b);
    return *reinterpret_cast<uint32_t*>(&h);
}
// async load [rows x 64 halves] tile into smem rows of 72 halves (pad)
__device__ __forceinline__ void ldta(const __half* __restrict__ src, size_t rowStride,
                                     __half* dst, int t, int nt, int rows) {
    for (int i = t; i < rows * 8; i += nt) {
        int r = i >> 3, c = i & 7;
        __pipeline_memcpy_async(&dst[r * 72 + c * 8], &src[(size_t)r * rowStride + c * 8], 16);
    }
}

typedef wmma::fragment<wmma::matrix_a, 16,16,16, __half, wmma::row_major> FragA;
typedef wmma::fragment<wmma::matrix_b, 16,16,16, __half, wmma::col_major> FragB;
typedef wmma::fragment<wmma::accumulator, 16,16,16, float> FragC;

// ---------------- weight prep ----------------
__global__ void k_prep_w2(const float* __restrict__ w2) {
    int idx = blockIdx.x * 256 + threadIdx.x;
    if (idx >= 36864) return;
    int o = idx / 576, r = idx % 576;                    // in: [o][c][tap]
    int c = r / 9, tap = r % 9;
    g_w2t[tap * 4096 + o * 64 + c] = __float2half_rn(w2[idx]);
}
__global__ void k_prep_w34(const float* __restrict__ w3, const float* __restrict__ w4) {
    int idx = blockIdx.x * 256 + threadIdx.x;            // 1048576
    int sel = idx >> 19, i = idx & 524287;
    int o = i >> 13, c = (i >> 7) & 63, p = i & 127;
    __half h = __float2half_rn(sel ? w4[i] : w3[i]);
    int d = p * 4096 + o * 64 + c;
    if (sel) g_w4[d] = h; else g_w3[d] = h;
}
__global__ void k_prep_w5(const float* __restrict__ w5) {
    int idx = blockIdx.x * 256 + threadIdx.x;            // 4194304
    int n = idx >> 13, k = idx & 8191;
    int c = k >> 7, p = k & 127;
    g_w5[n * 8192 + p * 64 + c] = __float2half_rn(w5[idx]);
}
__global__ void k_prep_w67(const float* __restrict__ w6, const float* __restrict__ w7) {
    int idx = blockIdx.x * 256 + threadIdx.x;            // 327680
    if (idx >= 327680) return;
    if (idx < 262144) g_w6[idx] = __float2half_rn(w6[idx]);
    else { int d = idx - 262144; g_w7[d] = __float2half_rn(w7[d]); }
}

// ---------------- conv1: bn0 + conv1 + bn1 + relu -> g_a1 [p][b][c] ----------------
// 8 batches per block, double-buffered input patch.
__global__ __launch_bounds__(256) void k_conv1(
    const float* __restrict__ x, const float* __restrict__ bn0,
    const float* __restrict__ w1, const float* __restrict__ b1,
    const float* __restrict__ bn1)
{
    __shared__ float h0s[2][180];
    __shared__ float w1s[576];
    __shared__ float s1s[64], t1s[64];
    int b0 = blockIdx.x * 8, t = threadIdx.x;
    if (t < 180) { h0s[0][t] = 0.f; h0s[1][t] = 0.f; }
    for (int i = t; i < 576; i += 256) w1s[i] = w1[i];
    if (t < 64) {
        float s = bn1[t] * rsqrtf(bn1[192 + t] + EPSF);
        s1s[t] = s;
        t1s[t] = bn1[64 + t] - bn1[128 + t] * s + b1[t] * s;
    }
    float s0 = bn0[0] * rsqrtf(bn0[3] + EPSF);
    float t0 = bn0[1] - bn0[2] * s0;
    __syncthreads();
    for (int bb = 0; bb < 8; bb++) {
        int b = b0 + bb, buf = bb & 1;
        if (t < 128) {
            int i = t >> 4, j = t & 15;
            h0s[buf][(i + 1) * 18 + (j + 1)] = x[b * 128 + j * 8 + i] * s0 + t0;
        }
        __syncthreads();
        for (int idx = t; idx < 2048; idx += 256) {
            int p = idx >> 4, o4 = (idx & 15) << 2;
            int i = p >> 4, j = p & 15;
            __half hh[4];
            #pragma unroll
            for (int q = 0; q < 4; q++) {
                int o = o4 + q;
                float acc = 0.f;
                #pragma unroll
                for (int di = 0; di < 3; di++)
                    #pragma unroll
                    for (int dj = 0; dj < 3; dj++)
                        acc = fmaf(h0s[buf][(i + di) * 18 + (j + dj)], w1s[o * 9 + di * 3 + dj], acc);
                hh[q] = __float2half_rn(fmaxf(fmaf(acc, s1s[o], t1s[o]), 0.f));
            }
            *reinterpret_cast<uint2*>(&g_a1[(size_t)p * 524288 + (size_t)b * 64 + o4]) =
                make_uint2(packh2(hh[0], hh[1]), packh2(hh[2], hh[3]));
        }
    }
}

// ---------------- fused conv2 + lc3 + lc4 (wmma fp16), 256-batch tiles ----------------
// grid (128 pixels, 32 btiles of 256), 512 threads (16 warps, 8x2 grid of 32x32 warp tiles).
// Per-tap buffer: A 0 (36864 = 256x72x2), W 36864 (9216) -> 46080. Two buffers.
#define CL_BUF 46080
#define CL_XH  92160
#define CL_W3  129024
#define CL_W4  138240
#define CL_BN  147456
#define CL_SMEM 148992
__global__ __launch_bounds__(512) void k_c2lc(
    const float* __restrict__ b2,  const float* __restrict__ bn2,
    const float* __restrict__ bn3, const float* __restrict__ bn4)
{
    extern __shared__ __align__(16) char smem[];
    float*  FB = reinterpret_cast<float*>(smem);                  // [256][68] f32, aliases buffers
    __half* XH = reinterpret_cast<__half*>(smem + CL_XH);         // [256][72]
    __half* W3 = reinterpret_cast<__half*>(smem + CL_W3);
    __half* W4 = reinterpret_cast<__half*>(smem + CL_W4);
    float*  BN = reinterpret_cast<float*>(smem + CL_BN);

    int p = blockIdx.x, b0 = blockIdx.y * 256, t = threadIdx.x;
    int w = t >> 5, wm = w & 7, wn = w >> 3;
    int i = p >> 4, j = p & 15;

    if (t < 64) {
        float s = bn2[t] * rsqrtf(bn2[192 + t] + EPSF);
        BN[t] = s;       BN[64 + t]  = bn2[64 + t] - bn2[128 + t] * s + b2[t] * s;
        s = bn3[t] * rsqrtf(bn3[192 + t] + EPSF);
        BN[128 + t] = s; BN[192 + t] = bn3[64 + t] - bn3[128 + t] * s;
        s = bn4[t] * rsqrtf(bn4[192 + t] + EPSF);
        BN[256 + t] = s; BN[320 + t] = bn4[64 + t] - bn4[128 + t] * s;
    }

    ldta(g_w3 + p * 4096, 64, W3, t, 512, 64);
    ldta(g_w4 + p * 4096, 64, W4, t, 512, 64);
    __pipeline_commit();

    int vt[9], nv = 0;
    #pragma unroll
    for (int tap = 0; tap < 9; tap++) {
        int ii = i + tap / 3 - 1, jj = j + tap % 3 - 1;
        if (ii >= 0 && ii < 8 && jj >= 0 && jj < 16) vt[nv++] = tap;
    }

    FragC acc[2][2];
    FragA ah;
    #pragma unroll
    for (int mt = 0; mt < 2; mt++)
        #pragma unroll
        for (int nt = 0; nt < 2; nt++) wmma::fill_fragment(acc[mt][nt], 0.f);

    auto issue = [&](int q, int bf) {
        int tap = vt[q];
        int pp = (i + tap / 3 - 1) * 16 + (j + tap % 3 - 1);
        char* B = smem + bf * CL_BUF;
        ldta(g_a1 + (size_t)pp * 524288 + (size_t)b0 * 64, 64,
             reinterpret_cast<__half*>(B), t, 512, 256);
        ldta(g_w2t + tap * 4096, 64, reinterpret_cast<__half*>(B + 36864), t, 512, 64);
        __pipeline_commit();
    };

    issue(0, 0);
    for (int q = 0; q < nv; q++) {
        if (q + 1 < nv) issue(q + 1, (q + 1) & 1);
        __pipeline_wait_prior((q + 1 < nv) ? 1 : 0);
        __syncthreads();
        char* B = smem + (q & 1) * CL_BUF;
        __half* AH = reinterpret_cast<__half*>(B);
        __half* WH = reinterpret_cast<__half*>(B + 36864);
        #pragma unroll
        for (int ks = 0; ks < 4; ks++) {
            FragB bhf[2];
            #pragma unroll
            for (int nt = 0; nt < 2; nt++)
                wmma::load_matrix_sync(bhf[nt], &WH[(wn * 32 + nt * 16) * 72 + ks * 16], 72);
            #pragma unroll
            for (int mt = 0; mt < 2; mt++) {
                wmma::load_matrix_sync(ah, &AH[(wm * 32 + mt * 16) * 72 + ks * 16], 72);
                #pragma unroll
                for (int nt = 0; nt < 2; nt++)
                    wmma::mma_sync(acc[mt][nt], ah, bhf[nt], acc[mt][nt]);
            }
        }
        __syncthreads();
    }

    // ---- conv2 epilogue -> XH ----
    #pragma unroll
    for (int mt = 0; mt < 2; mt++)
        #pragma unroll
        for (int nt = 0; nt < 2; nt++)
            wmma::store_matrix_sync(&FB[(wm * 32 + mt * 16) * 68 + wn * 32 + nt * 16],
                                    acc[mt][nt], 68, wmma::mem_row_major);
    __syncthreads();
    for (int q = 0; q < 8; q++) {
        int g = t + q * 512;
        int r = g >> 4, c4 = (g & 15) * 4;
        float4 v = *reinterpret_cast<float4*>(&FB[r * 68 + c4]);
        float* vp = &v.x;
        __half hh[4];
        #pragma unroll
        for (int qq = 0; qq < 4; qq++)
            hh[qq] = __float2half_rn(fmaxf(fmaf(vp[qq], BN[c4 + qq], BN[64 + c4 + qq]), 0.f));
        *reinterpret_cast<uint32_t*>(&XH[r * 72 + c4])     = packh2(hh[0], hh[1]);
        *reinterpret_cast<uint32_t*>(&XH[r * 72 + c4 + 2]) = packh2(hh[2], hh[3]);
    }
    __syncthreads();

    // ---- lc3 ----
    #pragma unroll
    for (int mt = 0; mt < 2; mt++)
        #pragma unroll
        for (int nt = 0; nt < 2; nt++) wmma::fill_fragment(acc[mt][nt], 0.f);
    #pragma unroll
    for (int ks = 0; ks < 4; ks++) {
        FragB bhf[2];
        #pragma unroll
        for (int nt = 0; nt < 2; nt++)
            wmma::load_matrix_sync(bhf[nt], &W3[(wn * 32 + nt * 16) * 72 + ks * 16], 72);
        #pragma unroll
        for (int mt = 0; mt < 2; mt++) {
            wmma::load_matrix_sync(ah, &XH[(wm * 32 + mt * 16) * 72 + ks * 16], 72);
            #pragma unroll
            for (int nt = 0; nt < 2; nt++)
                wmma::mma_sync(acc[mt][nt], ah, bhf[nt], acc[mt][nt]);
        }
    }
    __syncthreads();
    #pragma unroll
    for (int mt = 0; mt < 2; mt++)
        #pragma unroll
        for (int nt = 0; nt < 2; nt++)
            wmma::store_matrix_sync(&FB[(wm * 32 + mt * 16) * 68 + wn * 32 + nt * 16],
                                    acc[mt][nt], 68, wmma::mem_row_major);
    __syncthreads();
    for (int q = 0; q < 8; q++) {
        int g = t + q * 512;
        int r = g >> 4, c4 = (g & 15) * 4;
        float4 v = *reinterpret_cast<float4*>(&FB[r * 68 + c4]);
        float* vp = &v.x;
        __half hh[4];
        #pragma unroll
        for (int qq = 0; qq < 4; qq++)
            hh[qq] = __float2half_rn(fmaxf(fmaf(vp[qq], BN[128 + c4 + qq], BN[192 + c4 + qq]), 0.f));
        *reinterpret_cast<uint32_t*>(&XH[r * 72 + c4])     = packh2(hh[0], hh[1]);
        *reinterpret_cast<uint32_t*>(&XH[r * 72 + c4 + 2]) = packh2(hh[2], hh[3]);
    }
    __syncthreads();

    // ---- lc4 ----
    #pragma unroll
    for (int mt = 0; mt < 2; mt++)
        #pragma unroll
        for (int nt = 0; nt < 2; nt++) wmma::fill_fragment(acc[mt][nt], 0.f);
    #pragma unroll
    for (int ks = 0; ks < 4; ks++) {
        FragB bhf[2];
        #pragma unroll
        for (int nt = 0; nt < 2; nt++)
            wmma::load_matrix_sync(bhf[nt], &W4[(wn * 32 + nt * 16) * 72 + ks * 16], 72);
        #pragma unroll
        for (int mt = 0; mt < 2; mt++) {
            wmma::load_matrix_sync(ah, &XH[(wm * 32 + mt * 16) * 72 + ks * 16], 72);
            #pragma unroll
            for (int nt = 0; nt < 2; nt++)
                wmma::mma_sync(acc[mt][nt], ah, bhf[nt], acc[mt][nt]);
        }
    }
    __syncthreads();
    #pragma unroll
    for (int mt = 0; mt < 2; mt++)
        #pragma unroll
        for (int nt = 0; nt < 2; nt++)
            wmma::store_matrix_sync(&FB[(wm * 32 + mt * 16) * 68 + wn * 32 + nt * 16],
                                    acc[mt][nt], 68, wmma::mem_row_major);
    __syncthreads();
    for (int q = 0; q < 8; q++) {
        int g = t + q * 512;
        int r = g >> 4, c4 = (g & 15) * 4;
        float4 v = *reinterpret_cast<float4*>(&FB[r * 68 + c4]);
        float* vp = &v.x;
        __half hh[4];
        #pragma unroll
        for (int qq = 0; qq < 4; qq++)
            hh[qq] = __float2half_rn(fmaxf(fmaf(vp[qq], BN[256 + c4 + qq], BN[320 + c4 + qq]), 0.f));
        *reinterpret_cast<uint2*>(&g_a4[(size_t)(b0 + r) * 8192 + p * 64 + c4]) =
            make_uint2(packh2(hh[0], hh[1]), packh2(hh[2], hh[3]));
    }
}

// ---------------- generic wmma fc layer (fc5/fc6/fc7), pure fp16 ----------------
// sel: 0 = fc5 (a4->a5, K=8192), 1 = fc6 (a5->a6, K=512), 2 = fc7 (a6->a7 f32, K=512, N=128)
// Per-chunk buffer: A 0 (18432), W 18432 (18432) -> 36864. Two buffers.
#define FC_BUF 36864
#define FC_SMEM 73728
__global__ __launch_bounds__(512) void k_fcw(int sel, const float* __restrict__ bias,
                                             const float* __restrict__ bn)
{
    extern __shared__ __align__(16) char smem[];
    float* FB = reinterpret_cast<float*>(smem);             // [128][132]

    const __half *Ah, *Wh;
    __half *Oh = nullptr;
    float *Of = nullptr;
    int K;
    if (sel == 0)      { Ah = g_a4; Wh = g_w5; Oh = g_a5; K = 8192; }
    else if (sel == 1) { Ah = g_a5; Wh = g_w6; Oh = g_a6; K = 512; }
    else               { Ah = g_a6; Wh = g_w7; Of = g_a7; K = 512; }
    int N = (sel == 2) ? 128 : 512;
    int nch = K >> 6;

    int b0 = blockIdx.x * 128, nb = blockIdx.y * 128, t = threadIdx.x;
    int w = t >> 5, wm = w & 3, wn = w >> 2;                 // 16 warps: 4x4 of 32x32

    FragC acc[2][2];
    FragA ah;
    #pragma unroll
    for (int mt = 0; mt < 2; mt++)
        #pragma unroll
        for (int nt = 0; nt < 2; nt++) wmma::fill_fragment(acc[mt][nt], 0.f);

    auto issue = [&](int k, int bf) {
        char* B = smem + bf * FC_BUF;
        ldta(Ah + (size_t)b0 * K + k * 64, K, reinterpret_cast<__half*>(B), t, 512, 128);
        ldta(Wh + (size_t)nb * K + k * 64, K, reinterpret_cast<__half*>(B + 18432), t, 512, 128);
        __pipeline_commit();
    };

    issue(0, 0);
    for (int k = 0; k < nch; k++) {
        if (k + 1 < nch) issue(k + 1, (k + 1) & 1);
        __pipeline_wait_prior((k + 1 < nch) ? 1 : 0);
        __syncthreads();
        char* B = smem + (k & 1) * FC_BUF;
        __half* AH = reinterpret_cast<__half*>(B);
        __half* WH = reinterpret_cast<__half*>(B + 18432);
        #pragma unroll
        for (int ks = 0; ks < 4; ks++) {
            FragB bhf[2];
            #pragma unroll
            for (int nt = 0; nt < 2; nt++)
                wmma::load_matrix_sync(bhf[nt], &WH[(wn * 32 + nt * 16) * 72 + ks * 16], 72);
            #pragma unroll
            for (int mt = 0; mt < 2; mt++) {
                wmma::load_matrix_sync(ah, &AH[(wm * 32 + mt * 16) * 72 + ks * 16], 72);
                #pragma unroll
                for (int nt = 0; nt < 2; nt++)
                    wmma::mma_sync(acc[mt][nt], ah, bhf[nt], acc[mt][nt]);
            }
        }
        __syncthreads();
    }
    #pragma unroll
    for (int mt = 0; mt < 2; mt++)
        #pragma unroll
        for (int nt = 0; nt < 2; nt++)
            wmma::store_matrix_sync(&FB[(wm * 32 + mt * 16) * 132 + wn * 32 + nt * 16],
                                    acc[mt][nt], 132, wmma::mem_row_major);
    __syncthreads();
    float s = bn[0] * rsqrtf(bn[3] + EPSF);
    float tt = bn[1] - bn[2] * s;
    for (int q = 0; q < 8; q++) {
        int g = t + q * 512;
        int r = g >> 5, c4 = (g & 31) * 4;
        float4 v = *reinterpret_cast<float4*>(&FB[r * 132 + c4]);
        float* vp = &v.x;
        float z[4];
        #pragma unroll
        for (int qq = 0; qq < 4; qq++)
            z[qq] = fmaxf(fmaf(vp[qq] + __ldg(&bias[nb + c4 + qq]), s, tt), 0.f);
        if (Of) {
            *reinterpret_cast<float4*>(&Of[(size_t)(b0 + r) * N + nb + c4]) =
                make_float4(z[0], z[1], z[2], z[3]);
        } else {
            __half hh[4];
            #pragma unroll
            for (int qq = 0; qq < 4; qq++) hh[qq] = __float2half_rn(z[qq]);
            *reinterpret_cast<uint2*>(&Oh[(size_t)(b0 + r) * 512 + nb + c4]) =
                make_uint2(packh2(hh[0], hh[1]), packh2(hh[2], hh[3]));
        }
    }
}

// ---------------- fc8: (B,128) @ (8,128)^T + b8 -> d_out ----------------
__global__ __launch_bounds__(256) void k_fc8(const float* __restrict__ w8,
                                             const float* __restrict__ b8,
                                             float* __restrict__ out)
{
    int t = threadIdx.x;
    int b = blockIdx.x * 32 + (t >> 3), n = t & 7;
    const float* ar = &g_a7[b * 128];
    const float* wr = &w8[n * 128];
    float acc = 0.f;
    #pragma unroll 8
    for (int k = 0; k < 128; k++) acc = fmaf(ar[k], wr[k], acc);
    out[b * 8 + n] = acc + b8[n];
}

// ---------------- launch ----------------
extern "C" void kernel_launch(void* const* d_in, const int* in_sizes, int n_in,
                              void* d_out, int out_size)
{
    const float* x   = (const float*)d_in[0];
    const float* bn0 = (const float*)d_in[1];
    const float* w1  = (const float*)d_in[2];
    const float* b1  = (const float*)d_in[3];
    const float* bn1 = (const float*)d_in[4];
    const float* w2  = (const float*)d_in[5];
    const float* b2  = (const float*)d_in[6];
    const float* bn2 = (const float*)d_in[7];
    const float* w3  = (const float*)d_in[8];
    const float* bn3 = (const float*)d_in[9];
    const float* w4  = (const float*)d_in[10];
    const float* bn4 = (const float*)d_in[11];
    const float* w5  = (const float*)d_in[12];
    const float* b5  = (const float*)d_in[13];
    const float* bn5 = (const float*)d_in[14];
    const float* w6  = (const float*)d_in[15];
    const float* b6  = (const float*)d_in[16];
    const float* bn6 = (const float*)d_in[17];
    const float* w7  = (const float*)d_in[18];
    const float* b7  = (const float*)d_in[19];
    const float* bn7 = (const float*)d_in[20];
    const float* w8  = (const float*)d_in[21];
    const float* b8  = (const float*)d_in[22];
    float* out = (float*)d_out;

    cudaFuncSetAttribute(k_c2lc, cudaFuncAttributeMaxDynamicSharedMemorySize, CL_SMEM);
    cudaFuncSetAttribute(k_fcw,  cudaFuncAttributeMaxDynamicSharedMemorySize, FC_SMEM);

    k_prep_w2 <<<144,   256>>>(w2);
    k_prep_w34<<<4096,  256>>>(w3, w4);
    k_prep_w5 <<<16384, 256>>>(w5);
    k_prep_w67<<<1280,  256>>>(w6, w7);

    k_conv1<<<1024, 256>>>(x, bn0, w1, b1, bn1);
    k_c2lc<<<dim3(128, 32), 512, CL_SMEM>>>(b2, bn2, bn3, bn4);
    k_fcw<<<dim3(64, 4), 512, FC_SMEM>>>(0, b5, bn5);
    k_fcw<<<dim3(64, 4), 512, FC_SMEM>>>(1, b6, bn6);
    k_fcw<<<dim3(64, 1), 512, FC_SMEM>>>(2, b7, bn7);
    k_fc8<<<256, 256>>>(w8, b8, out);
}